// round 8
// baseline (speedup 1.0000x reference)
#include <cuda_runtime.h>
#include <cstdint>

// Fixed problem shapes
#define BB 8
#define CC 3
#define HH 720
#define WW 1280
#define HWP (HH * WW)          // 921600

// Tiling: warp = one row of 128 px (lane-linear x, 4 px/thread strided by 32)
#define TW 128                 // tile width  (1280 / 128 = 10)
#define TH 8                   // tile height (720 / 8 = 90); warp w -> row w
#define RR 4                   // halo radius; |flow|>4 takes global fallback
#define SWX 137                // staged cols: TW + 2R + 1 (x1 = x0+1 unclamped)
#define SHY 17                 // staged rows: TH + 2R + 1
#define PITCH 161              // >= SWX and PITCH % 32 == 1  -> bank = (lane+dx+dy+c) mod 32
#define PLANE (SHY * PITCH)    // 2737 floats per channel plane
#define NTHREADS 256

__global__ __launch_bounds__(NTHREADS)
void backwarp_lane(const float* __restrict__ img,
                   const float* __restrict__ flow,
                   float* __restrict__ out) {
    __shared__ float sm[CC * PLANE];      // 3 * 2737 * 4 = 32844 B

    const int tid  = threadIdx.x;
    const int wid  = tid >> 5;            // 0..7
    const int lane = tid & 31;

    const int tx0 = blockIdx.x * TW;
    const int ty0 = blockIdx.y * TH;
    const int b   = blockIdx.z;

    const float* imb = img + (size_t)b * CC * HWP;
    const float* im0 = imb;
    const float* im1 = imb + HWP;
    const float* im2 = imb + 2 * HWP;

    // ---- Stage tile + halo, border-clamped. LDG coalesced, STS conflict-free ----
    #pragma unroll 1
    for (int sy = wid; sy < SHY; sy += 8) {
        int gy = min(max(ty0 - RR + sy, 0), HH - 1);
        const float* r0 = im0 + gy * WW;
        const float* r1 = im1 + gy * WW;
        const float* r2 = im2 + gy * WW;
        float* s = sm + sy * PITCH;
        #pragma unroll 1
        for (int sx = lane; sx < SWX; sx += 32) {
            int gx = min(max(tx0 - RR + sx, 0), WW - 1);
            s[sx]             = __ldg(r0 + gx);
            s[PLANE + sx]     = __ldg(r1 + gx);
            s[2 * PLANE + sx] = __ldg(r2 + gx);
        }
    }
    __syncthreads();

    // ---- Gather: warp handles row ty0+wid, lane-linear x ----
    const int py   = ty0 + wid;
    const int pxl  = tx0 + lane;
    const int pix0 = py * WW + pxl;

    const float* flb = flow + (size_t)b * 2 * HWP;
    float* ob = out + (size_t)b * CC * HWP;

    #pragma unroll
    for (int j = 0; j < 4; ++j) {
        const int pix = pix0 + 32 * j;
        const int xi  = pxl + 32 * j;

        float fx = __ldg(flb + pix);
        float fy = __ldg(flb + HWP + pix);

        float x = fminf(fmaxf((float)xi + fx, 0.0f), (float)(WW - 1));
        float y = fminf(fmaxf((float)py + fy, 0.0f), (float)(HH - 1));
        float x0f = floorf(x);
        float y0f = floorf(y);
        float wx = x - x0f;
        float wy = y - y0f;
        int x0 = (int)x0f;
        int y0 = (int)y0f;

        int lx0 = x0 - tx0 + RR;
        int ly0 = y0 - ty0 + RR;

        float r0v, r1v, r2v;
        if ((unsigned)lx0 <= (SWX - 2) && (unsigned)ly0 <= (SHY - 2)) {
            // One address, 12 LDS with immediate offsets; halo replicates borders
            const float* p = sm + ly0 * PITCH + lx0;
            float top, bot;
            {
                float v00 = p[0], v01 = p[1], v10 = p[PITCH], v11 = p[PITCH + 1];
                top = v00 + wx * (v01 - v00);
                bot = v10 + wx * (v11 - v10);
                r0v = top + wy * (bot - top);
            }
            {
                float v00 = p[PLANE], v01 = p[PLANE + 1],
                      v10 = p[PLANE + PITCH], v11 = p[PLANE + PITCH + 1];
                top = v00 + wx * (v01 - v00);
                bot = v10 + wx * (v11 - v10);
                r1v = top + wy * (bot - top);
            }
            {
                float v00 = p[2 * PLANE], v01 = p[2 * PLANE + 1],
                      v10 = p[2 * PLANE + PITCH], v11 = p[2 * PLANE + PITCH + 1];
                top = v00 + wx * (v01 - v00);
                bot = v10 + wx * (v11 - v10);
                r2v = top + wy * (bot - top);
            }
        } else {
            // Rare |flow|>4 fallback: clamped global gather
            int x1 = min(x0 + 1, WW - 1);
            int y1 = min(y0 + 1, HH - 1);
            int i00 = y0 * WW + x0;
            int i01 = y0 * WW + x1;
            int i10 = y1 * WW + x0;
            int i11 = y1 * WW + x1;
            float top, bot;
            top = __ldg(im0 + i00) + wx * (__ldg(im0 + i01) - __ldg(im0 + i00));
            bot = __ldg(im0 + i10) + wx * (__ldg(im0 + i11) - __ldg(im0 + i10));
            r0v = top + wy * (bot - top);
            top = __ldg(im1 + i00) + wx * (__ldg(im1 + i01) - __ldg(im1 + i00));
            bot = __ldg(im1 + i10) + wx * (__ldg(im1 + i11) - __ldg(im1 + i10));
            r1v = top + wy * (bot - top);
            top = __ldg(im2 + i00) + wx * (__ldg(im2 + i01) - __ldg(im2 + i00));
            bot = __ldg(im2 + i10) + wx * (__ldg(im2 + i11) - __ldg(im2 + i10));
            r2v = top + wy * (bot - top);
        }

        ob[pix]            = r0v;
        ob[HWP + pix]      = r1v;
        ob[2 * HWP + pix]  = r2v;
    }
}

extern "C" void kernel_launch(void* const* d_in, const int* in_sizes, int n_in,
                              void* d_out, int out_size) {
    const float* img  = (const float*)d_in[0];
    const float* flow = (const float*)d_in[1];
    float* out = (float*)d_out;

    dim3 grid(WW / TW, HH / TH, BB);   // (10, 90, 8) = 7200 blocks
    backwarp_lane<<<grid, NTHREADS>>>(img, flow, out);
}

// round 9
// speedup vs baseline: 1.4593x; 1.4593x over previous
#include <cuda_runtime.h>
#include <cstdint>

// Fixed problem shapes
#define BB 8
#define CC 3
#define HH 720
#define WW 1280
#define HWP (HH * WW)          // 921600

// Tiling: 64x16 tile, warp w covers rows w and w+8, lane-linear x (2 cols/row)
#define TW 64                  // 1280 / 64 = 20
#define TH 16                  // 720 / 16 = 45
#define RR 4                   // halo radius; |flow|>4 -> global fallback
#define SWX 73                 // TW + 2*RR + 1  (x0+1 unclamped inside)
#define SHY 25                 // TH + 2*RR + 1
#define PITCH 73               // odd pitch: bank = (9*ly + lx) mod 32, shifted identity
#define PLANE (SHY * PITCH)    // 1825 floats per channel plane
#define NTHREADS 256

__global__ __launch_bounds__(NTHREADS)
void backwarp_mlp(const float* __restrict__ img,
                  const float* __restrict__ flow,
                  float* __restrict__ out) {
    __shared__ float sm[CC * PLANE];      // 3 * 1825 * 4 = 21900 B

    const int tid  = threadIdx.x;
    const int wid  = tid >> 5;            // 0..7
    const int lane = tid & 31;

    const int tx0 = blockIdx.x * TW;
    const int ty0 = blockIdx.y * TH;
    const int b   = blockIdx.z;

    const float* imb = img + (size_t)b * CC * HWP;
    const float* im0 = imb;
    const float* im1 = imb + HWP;
    const float* im2 = imb + 2 * HWP;
    const float* flb = flow + (size_t)b * 2 * HWP;

    // ---- Prefetch flow for this thread's 4 pixels (latency hides under staging) ----
    const int pyA  = ty0 + wid;           // rows wid and wid+8
    const int pyB  = pyA + 8;
    const int pixA = pyA * WW + tx0 + lane;
    const int pixB = pyB * WW + tx0 + lane;
    float fx0 = __ldg(flb + pixA);
    float fx1 = __ldg(flb + pixA + 32);
    float fx2 = __ldg(flb + pixB);
    float fx3 = __ldg(flb + pixB + 32);
    float fy0 = __ldg(flb + HWP + pixA);
    float fy1 = __ldg(flb + HWP + pixA + 32);
    float fy2 = __ldg(flb + HWP + pixB);
    float fy3 = __ldg(flb + HWP + pixB + 32);

    // ---- Stage tile + halo: per-row batched 9 LDG -> 9 STS (MLP ~9) ----
    const bool tail = (lane < SWX - 64);  // lane < 9: third column valid
    #pragma unroll
    for (int rr = 0; rr < 4; ++rr) {
        int sy = wid + rr * 8;            // warps cover rows 0..23; warp 0 also 24
        if (rr == 3 && wid != 0) break;
        if (rr == 3) sy = 24;
        int gy = min(max(ty0 - RR + sy, 0), HH - 1);
        int gx0 = max(tx0 - RR + lane, 0);               // high side always < W
        int gx1 = tx0 - RR + lane + 32;                  // never clamps
        int gx2 = min(tx0 - RR + lane + 64, WW - 1);     // low side always >= 0
        const float* r0 = im0 + gy * WW;
        const float* r1 = im1 + gy * WW;
        const float* r2 = im2 + gy * WW;
        float a0 = __ldg(r0 + gx0);
        float a1 = __ldg(r0 + gx1);
        float a2 = tail ? __ldg(r0 + gx2) : 0.f;
        float b0 = __ldg(r1 + gx0);
        float b1 = __ldg(r1 + gx1);
        float b2 = tail ? __ldg(r1 + gx2) : 0.f;
        float c0 = __ldg(r2 + gx0);
        float c1 = __ldg(r2 + gx1);
        float c2 = tail ? __ldg(r2 + gx2) : 0.f;
        float* s = sm + sy * PITCH;
        s[lane]                  = a0;
        s[lane + 32]             = a1;
        s[PLANE + lane]          = b0;
        s[PLANE + lane + 32]     = b1;
        s[2 * PLANE + lane]      = c0;
        s[2 * PLANE + lane + 32] = c1;
        if (tail) {
            s[lane + 64]             = a2;
            s[PLANE + lane + 64]     = b2;
            s[2 * PLANE + lane + 64] = c2;
        }
    }
    __syncthreads();

    float* ob = out + (size_t)b * CC * HWP;

    // ---- Gather helper: one smem address, 12 LDS immediate-offset ----
    auto gather = [&](int xi, int yi, int pix, float fx, float fy) {
        float x = fminf(fmaxf((float)xi + fx, 0.0f), (float)(WW - 1));
        float y = fminf(fmaxf((float)yi + fy, 0.0f), (float)(HH - 1));
        float x0f = floorf(x);
        float y0f = floorf(y);
        float wx = x - x0f;
        float wy = y - y0f;
        int x0 = (int)x0f;
        int y0 = (int)y0f;
        int lx0 = x0 - tx0 + RR;
        int ly0 = y0 - ty0 + RR;
        float r0v, r1v, r2v;
        if ((unsigned)lx0 <= (SWX - 2) && (unsigned)ly0 <= (SHY - 2)) {
            const float* p = sm + ly0 * PITCH + lx0;
            float v00 = p[0], v01 = p[1], v10 = p[PITCH], v11 = p[PITCH + 1];
            float w00 = p[PLANE], w01 = p[PLANE + 1],
                  w10 = p[PLANE + PITCH], w11 = p[PLANE + PITCH + 1];
            float u00 = p[2 * PLANE], u01 = p[2 * PLANE + 1],
                  u10 = p[2 * PLANE + PITCH], u11 = p[2 * PLANE + PITCH + 1];
            float top, bot;
            top = v00 + wx * (v01 - v00);
            bot = v10 + wx * (v11 - v10);
            r0v = top + wy * (bot - top);
            top = w00 + wx * (w01 - w00);
            bot = w10 + wx * (w11 - w10);
            r1v = top + wy * (bot - top);
            top = u00 + wx * (u01 - u00);
            bot = u10 + wx * (u11 - u10);
            r2v = top + wy * (bot - top);
        } else {
            int x1 = min(x0 + 1, WW - 1);
            int y1 = min(y0 + 1, HH - 1);
            int i00 = y0 * WW + x0;
            int i01 = y0 * WW + x1;
            int i10 = y1 * WW + x0;
            int i11 = y1 * WW + x1;
            float top, bot;
            top = __ldg(im0 + i00) + wx * (__ldg(im0 + i01) - __ldg(im0 + i00));
            bot = __ldg(im0 + i10) + wx * (__ldg(im0 + i11) - __ldg(im0 + i10));
            r0v = top + wy * (bot - top);
            top = __ldg(im1 + i00) + wx * (__ldg(im1 + i01) - __ldg(im1 + i00));
            bot = __ldg(im1 + i10) + wx * (__ldg(im1 + i11) - __ldg(im1 + i10));
            r1v = top + wy * (bot - top);
            top = __ldg(im2 + i00) + wx * (__ldg(im2 + i01) - __ldg(im2 + i00));
            bot = __ldg(im2 + i10) + wx * (__ldg(im2 + i11) - __ldg(im2 + i10));
            r2v = top + wy * (bot - top);
        }
        ob[pix]           = r0v;
        ob[HWP + pix]     = r1v;
        ob[2 * HWP + pix] = r2v;
    };

    gather(tx0 + lane,      pyA, pixA,      fx0, fy0);
    gather(tx0 + lane + 32, pyA, pixA + 32, fx1, fy1);
    gather(tx0 + lane,      pyB, pixB,      fx2, fy2);
    gather(tx0 + lane + 32, pyB, pixB + 32, fx3, fy3);
}

extern "C" void kernel_launch(void* const* d_in, const int* in_sizes, int n_in,
                              void* d_out, int out_size) {
    const float* img  = (const float*)d_in[0];
    const float* flow = (const float*)d_in[1];
    float* out = (float*)d_out;

    dim3 grid(WW / TW, HH / TH, BB);   // (20, 45, 8) = 7200 blocks
    backwarp_mlp<<<grid, NTHREADS>>>(img, flow, out);
}